// round 15
// baseline (speedup 1.0000x reference)
#include <cuda_runtime.h>
#include <cuda_fp16.h>
#include <stdint.h>

#define D_MODEL 1024
#define NUM_HEAD 16
#define HEAD_DIM 64
#define BATCH 2
#define SEQ 2048
#define MTOT 4096

// fp16 scratch
__device__ __half g_Q[(size_t)MTOT * D_MODEL];
__device__ __half g_K[(size_t)MTOT * D_MODEL];
__device__ __half g_VT[(size_t)BATCH * D_MODEL * SEQ];  // [b][d_global][token]
__device__ __half g_O[(size_t)MTOT * D_MODEL];
__device__ __half g_X[(size_t)MTOT * D_MODEL];
__device__ __half g_W[(size_t)4 * D_MODEL * D_MODEL];

__device__ __forceinline__ float ex2(float x) {
    float y;
    asm("ex2.approx.ftz.f32 %0, %1;" : "=f"(y) : "f"(x));
    return y;
}
__device__ __forceinline__ uint32_t ex2_h2(uint32_t x) {
    uint32_t y;
    asm("ex2.approx.f16x2 %0, %1;" : "=r"(y) : "r"(x));
    return y;
}

__device__ __forceinline__ void mma_f16(float d[4], const uint32_t a[4],
                                        const uint32_t b[2], const float c[4]) {
    asm volatile(
        "mma.sync.aligned.m16n8k16.row.col.f32.f16.f16.f32 "
        "{%0,%1,%2,%3}, {%4,%5,%6,%7}, {%8,%9}, {%10,%11,%12,%13};\n"
        : "=f"(d[0]), "=f"(d[1]), "=f"(d[2]), "=f"(d[3])
        : "r"(a[0]), "r"(a[1]), "r"(a[2]), "r"(a[3]),
          "r"(b[0]), "r"(b[1]),
          "f"(c[0]), "f"(c[1]), "f"(c[2]), "f"(c[3]));
}

#define LDSMX4(R0, R1, R2, R3, ADDR)                                           \
    asm volatile("ldmatrix.sync.aligned.m8n8.x4.shared.b16 {%0,%1,%2,%3}, [%4];" \
                 : "=r"(R0), "=r"(R1), "=r"(R2), "=r"(R3) : "r"(ADDR))

__device__ __forceinline__ uint32_t s2u(const void* p) {
    return (uint32_t)__cvta_generic_to_shared(p);
}
__device__ __forceinline__ void cp16(uint32_t s, const void* g) {
    asm volatile("cp.async.cg.shared.global [%0], [%1], 16;" :: "r"(s), "l"(g));
}
__device__ __forceinline__ void cpcommit() {
    asm volatile("cp.async.commit_group;");
}
template <int N> __device__ __forceinline__ void cpwait() {
    asm volatile("cp.async.wait_group %0;" :: "n"(N));
}

// ---------------------------------------------------------------------------
__global__ __launch_bounds__(256) void preround(
    const float* __restrict__ x,
    const float* __restrict__ Wq, const float* __restrict__ Wk,
    const float* __restrict__ Wv, const float* __restrict__ Wo,
    __half* __restrict__ Xh, __half* __restrict__ Wh)
{
    const int bid = blockIdx.x;
    const float* src;
    __half* dst;
    size_t off;
    if (bid < 1024) {
        src = x; dst = Xh; off = (size_t)bid * 4096;
    } else {
        const int w = (bid - 1024) >> 8;
        const int lb = (bid - 1024) & 255;
        src = (w == 0) ? Wq : (w == 1) ? Wk : (w == 2) ? Wv : Wo;
        dst = Wh + (size_t)w * 1048576;
        off = (size_t)lb * 4096;
    }
    const float4* s4 = (const float4*)(src + off);
    __half2* d2 = (__half2*)(dst + off);
#pragma unroll
    for (int j = 0; j < 4; j++) {
        const int idx = threadIdx.x + j * 256;
        float4 v = s4[idx];
        d2[idx * 2] = __floats2half2_rn(v.x, v.y);
        d2[idx * 2 + 1] = __floats2half2_rn(v.z, v.w);
    }
}

// ---------------------------------------------------------------------------
// fp16 GEMM (NT): 128x128x64 stages, 3-stage cp.async pipeline (16 stages
// total -> half the barriers of BK=32). Row stride 72 halfs (144 B): LDSM
// 8-row offsets 16r mod 128 distinct -> conflict-free. ldmatrix.x4 frags.
// ---------------------------------------------------------------------------
#define GROWH 72
#define GTHh (128 * GROWH)     // 9216 halfs per operand tile
#define GSTGHh (2 * GTHh)      // 18432 halfs per stage
#define GSTGB (GSTGHh * 2)     // 36864 bytes per stage

__global__ __launch_bounds__(256, 2) void gemm_f16(
    const __half* __restrict__ A,
    const __half* __restrict__ W0, const __half* __restrict__ W1,
    const __half* __restrict__ W2,
    const float* __restrict__ b0p, const float* __restrict__ b1p,
    const float* __restrict__ b2p,
    void* __restrict__ C0, void* __restrict__ C1, void* __restrict__ C2,
    int m0_, int m1_, int m2_)
{
    extern __shared__ __half smh[];
    const int z = blockIdx.z;
    const __half* W = (z == 0) ? W0 : (z == 1) ? W1 : W2;
    const float* bias = (z == 0) ? b0p : (z == 1) ? b1p : b2p;
    void* C = (z == 0) ? C0 : (z == 1) ? C1 : C2;
    const int mode = (z == 0) ? m0_ : (z == 1) ? m1_ : m2_;
    const float oscale = (mode == 1) ? 0.18033688011112042f : 1.0f;

    const int tid = threadIdx.x;
    const int warp = tid >> 5, lane = tid & 31;
    const int wm = warp >> 1, wn = warp & 1;
    const int tm = lane >> 2, tk = lane & 3;
    const int grp = lane >> 3, r8 = lane & 7;

    const __half* Ab = A + (size_t)(blockIdx.y * 128) * D_MODEL;
    const __half* Wb = W + (size_t)(blockIdx.x * 128) * D_MODEL;

    const int lr = tid >> 1;         // 0..127
    const int lkh = (tid & 1) * 32;  // half offset 0 or 32

    const uint32_t sAb = s2u(smh + lr * GROWH + lkh);
    const uint32_t sBb = sAb + GTHh * 2;
    const __half* gA = Ab + (size_t)lr * D_MODEL + lkh;
    const __half* gW = Wb + (size_t)lr * D_MODEL + lkh;

    const uint32_t aoff = ((((grp & 1) * 8 + r8) * GROWH) + (grp >> 1) * 8) * 2;
    const uint32_t boff = ((((grp >> 1) * 8 + r8) * GROWH) + (grp & 1) * 8) * 2;
    const uint32_t aBase = s2u(smh) + (wm * 32) * GROWH * 2 + aoff;
    const uint32_t bBase = s2u(smh) + GTHh * 2 + (wn * 64) * GROWH * 2 + boff;

    float acc[2][8][4];
#pragma unroll
    for (int mt = 0; mt < 2; mt++)
#pragma unroll
        for (int nt = 0; nt < 8; nt++)
#pragma unroll
            for (int i = 0; i < 4; i++) acc[mt][nt][i] = 0.0f;

    // prologue: stages 0,1 -> bufs 0,1
#pragma unroll
    for (int s = 0; s < 2; s++) {
#pragma unroll
        for (int c = 0; c < 4; c++) {
            cp16(sAb + s * GSTGB + c * 16, gA + s * 64 + c * 8);
            cp16(sBb + s * GSTGB + c * 16, gW + s * 64 + c * 8);
        }
        cpcommit();
    }

#define GEMM_STAGE(SBUF, LBUF, KO, DOLOAD)                                    \
    {                                                                          \
        cpwait<1>();                                                           \
        __syncthreads();                                                       \
        if (DOLOAD) {                                                          \
            _Pragma("unroll")                                                  \
            for (int c = 0; c < 4; c++) {                                      \
                cp16(sAb + (LBUF) * GSTGB + c * 16, gA + (KO) + c * 8);        \
                cp16(sBb + (LBUF) * GSTGB + c * 16, gW + (KO) + c * 8);        \
            }                                                                  \
        }                                                                      \
        cpcommit();                                                            \
        const uint32_t sa_ = aBase + (SBUF) * GSTGB;                           \
        const uint32_t sb_ = bBase + (SBUF) * GSTGB;                           \
        _Pragma("unroll")                                                      \
        for (int ks = 0; ks < 4; ks++) {                                       \
            uint32_t af[2][4], bf[8][2];                                       \
            _Pragma("unroll")                                                  \
            for (int mt = 0; mt < 2; mt++)                                     \
                LDSMX4(af[mt][0], af[mt][1], af[mt][2], af[mt][3],             \
                       sa_ + mt * (16 * GROWH * 2) + ks * 32);                 \
            _Pragma("unroll")                                                  \
            for (int np = 0; np < 4; np++)                                     \
                LDSMX4(bf[2 * np][0], bf[2 * np][1],                           \
                       bf[2 * np + 1][0], bf[2 * np + 1][1],                   \
                       sb_ + np * (16 * GROWH * 2) + ks * 32);                 \
            _Pragma("unroll")                                                  \
            for (int mt = 0; mt < 2; mt++)                                     \
                _Pragma("unroll")                                              \
                for (int nt = 0; nt < 8; nt++)                                 \
                    mma_f16(acc[mt][nt], af[mt], bf[nt], acc[mt][nt]);         \
        }                                                                      \
    }

    // 16 stages of k=64; loads run 2 ahead. Buffer pattern period 3.
    int koc = 128;  // stage-2 k offset in halfs
    for (int c = 0; c < 4; c++) {
        GEMM_STAGE(0, 2, koc, 1)
        GEMM_STAGE(1, 0, koc + 64, 1)
        GEMM_STAGE(2, 1, koc + 128, 1)
        koc += 192;
    }
    GEMM_STAGE(0, 2, koc, 1)       // it=12, loads stage 14 (ko=896)
    GEMM_STAGE(1, 0, koc + 64, 1)  // it=13, loads stage 15 (ko=960)
    GEMM_STAGE(2, 0, 0, 0)         // it=14
    GEMM_STAGE(0, 0, 0, 0)         // it=15
#undef GEMM_STAGE

    // ---- epilogue ----
#pragma unroll
    for (int mt = 0; mt < 2; mt++) {
        const int r0 = blockIdx.y * 128 + wm * 32 + mt * 16 + tm;
#pragma unroll
        for (int nt = 0; nt < 8; nt++) {
            const int col = blockIdx.x * 128 + wn * 64 + nt * 8 + 2 * tk;
            const float bb0 = bias[col], bb1 = bias[col + 1];
            float v0 = (acc[mt][nt][0] + bb0) * oscale;
            float v1 = (acc[mt][nt][1] + bb1) * oscale;
            float v2 = (acc[mt][nt][2] + bb0) * oscale;
            float v3 = (acc[mt][nt][3] + bb1) * oscale;
            if (mode == 0) {
                float* Cf = (float*)C;
                *(float2*)(Cf + (size_t)r0 * D_MODEL + col) = make_float2(v0, v1);
                *(float2*)(Cf + (size_t)(r0 + 8) * D_MODEL + col) =
                    make_float2(v2, v3);
            } else if (mode != 3) {
                __half* Ch = (__half*)C;
                *(__half2*)(Ch + (size_t)r0 * D_MODEL + col) =
                    __floats2half2_rn(v0, v1);
                *(__half2*)(Ch + (size_t)(r0 + 8) * D_MODEL + col) =
                    __floats2half2_rn(v2, v3);
            } else {
                const int bb = r0 >> 11;
                const int tok = r0 & 2047;
                __half* vb = (__half*)C + ((size_t)(bb * 1024 + col)) * 2048 + tok;
                vb[0] = __float2half_rn(v0);
                vb[2048] = __float2half_rn(v1);
                vb[8] = __float2half_rn(v2);
                vb[2048 + 8] = __float2half_rn(v3);
            }
        }
    }
}

// ---------------------------------------------------------------------------
// fp16 flash attention: 8 warps, BQ=128, BKT=64. Double-buffered K/V with
// fused {K,V} commit groups: 1 cpwait + 2 syncthreads per k-tile (was 2+4).
// Row stride 72 halfs; ldmatrix.x4 frags; f16x2 exp softmax.
// Smem halfs: Qs[128*72] Ps[128*72] + 2x(Ks[64*72]+Vt[64*72]) = 73728 B.
// ---------------------------------------------------------------------------
#define SF 72
#define KVBUF (2 * 64 * SF)   // halfs per K+V buffer pair: 9216
#define KVBUFB (KVBUF * 2)    // 18432 bytes

__global__ __launch_bounds__(256, 2) void flash_f16(
    const __half* __restrict__ Qg, const __half* __restrict__ Kg,
    const __half* __restrict__ VTg, __half* __restrict__ Og)
{
    extern __shared__ __half smh[];
    __half* Qs = smh;                    // 128*72
    __half* Ps = smh + 128 * SF;         // 9216
    __half* KV0 = smh + 2 * 128 * SF;    // buffers: [Ks 64*72][Vt 64*72] x2

    const int tid = threadIdx.x;
    const int warp = tid >> 5, lane = tid & 31;
    const int tm = lane >> 2, tk = lane & 3;
    const int grp = lane >> 3, r8 = lane & 7;
    const int b = blockIdx.y >> 4, h = blockIdx.y & 15;
    const int q0 = blockIdx.x * 128;

    const __half* Qb = Qg + (size_t)(b * SEQ + q0) * D_MODEL + h * HEAD_DIM;
    const __half* Kb = Kg + (size_t)(b * SEQ) * D_MODEL + h * HEAD_DIM;

    // ---- K/VT loader fixed offsets ----
    const int kr = tid >> 2;
    const int kc = (tid & 3) * 16;
    const uint32_t sK = s2u(KV0 + kr * SF + kc);
    const uint32_t sV = sK + 64 * SF * 2;
    const __half* gK = Kb + (size_t)kr * D_MODEL + kc;
    const __half* gV = VTg + ((size_t)(b * 1024 + h * HEAD_DIM + kr)) * 2048 + kc;

    // ---- prologue: group0 = {Q, K0, V0}; group1 = {K1, V1} ----
    {
        const int qr = tid >> 1;
        const int qc = (tid & 1) * 32;
        uint32_t sq = s2u(Qs + qr * SF + qc);
        const __half* gq = Qb + (size_t)qr * D_MODEL + qc;
        cp16(sq, gq); cp16(sq + 16, gq + 8);
        cp16(sq + 32, gq + 16); cp16(sq + 48, gq + 24);
    }
    cp16(sK, gK); cp16(sK + 16, gK + 8);
    cp16(sV, gV); cp16(sV + 16, gV + 8);
    cpcommit();
    gK += 64 * D_MODEL; gV += 64;
    cp16(sK + KVBUFB, gK); cp16(sK + KVBUFB + 16, gK + 8);
    cp16(sV + KVBUFB, gV); cp16(sV + KVBUFB + 16, gV + 8);
    cpcommit();
    gK += 64 * D_MODEL; gV += 64;

    // ---- LDSM lane bases (bytes) ----
    const uint32_t aoff = ((((grp & 1) * 8 + r8) * SF) + (grp >> 1) * 8) * 2;
    const uint32_t boff = ((((grp >> 1) * 8 + r8) * SF) + (grp & 1) * 8) * 2;
    const uint32_t aQ = s2u(Qs + warp * 16 * SF) + aoff;
    const uint32_t aP = s2u(Ps + warp * 16 * SF) + aoff;
    const uint32_t bK0 = s2u(KV0) + boff;
    const uint32_t bV0 = s2u(KV0 + 64 * SF) + boff;

    __half* pPst = Ps + (warp * 16 + tm) * SF + 2 * tk;

    float s[8][4], acc[8][4], mi[2], li[2];
#pragma unroll
    for (int nt = 0; nt < 8; nt++)
#pragma unroll
        for (int i = 0; i < 4; i++) acc[nt][i] = 0.0f;
    mi[0] = mi[1] = -1e30f;
    li[0] = li[1] = 0.0f;

    const int NKT = SEQ / 64;  // 32

    for (int it = 0; it < NKT; it++) {
        const uint32_t bufo = (uint32_t)(it & 1) * KVBUFB;
        cpwait<1>();          // {K,V}(it) complete
        __syncthreads();

        // ---- S = Q @ K^T ----
#pragma unroll
        for (int nt = 0; nt < 8; nt++)
#pragma unroll
            for (int i = 0; i < 4; i++) s[nt][i] = 0.0f;

#pragma unroll
        for (int ks = 0; ks < 4; ks++) {
            uint32_t af[4], bf[8][2];
            LDSMX4(af[0], af[1], af[2], af[3], aQ + ks * 32);
#pragma unroll
            for (int np = 0; np < 4; np++)
                LDSMX4(bf[2 * np][0], bf[2 * np][1],
                       bf[2 * np + 1][0], bf[2 * np + 1][1],
                       bK0 + bufo + np * (16 * SF * 2) + ks * 32);
#pragma unroll
            for (int nt = 0; nt < 8; nt++)
                mma_f16(s[nt], af, bf[nt], s[nt]);
        }

        // ---- online softmax (log2 domain; f16x2 exp; P stored fp16) ----
#pragma unroll
        for (int rh = 0; rh < 2; rh++) {
            float mx = -1e30f;
#pragma unroll
            for (int nt = 0; nt < 8; nt++)
#pragma unroll
                for (int j = 0; j < 2; j++)
                    mx = fmaxf(mx, s[nt][rh * 2 + j]);
            mx = fmaxf(mx, __shfl_xor_sync(0xffffffffu, mx, 1));
            mx = fmaxf(mx, __shfl_xor_sync(0xffffffffu, mx, 2));
            const float mn = fmaxf(mi[rh], mx);
            const float corr = ex2(mi[rh] - mn);
            mi[rh] = mn;
            float sum = 0.0f;
#pragma unroll
            for (int nt = 0; nt < 8; nt++) {
                __half2 t = __floats2half2_rn(s[nt][rh * 2] - mn,
                                              s[nt][rh * 2 + 1] - mn);
                uint32_t p2 = ex2_h2(*(uint32_t*)&t);
                *(uint32_t*)(pPst + rh * (8 * SF) + nt * 8) = p2;
                __half2 ph = *(__half2*)&p2;
                sum += __low2float(ph) + __high2float(ph);
            }
            sum += __shfl_xor_sync(0xffffffffu, sum, 1);
            sum += __shfl_xor_sync(0xffffffffu, sum, 2);
            li[rh] = li[rh] * corr + sum;
#pragma unroll
            for (int nt = 0; nt < 8; nt++)
#pragma unroll
                for (int j = 0; j < 2; j++)
                    acc[nt][rh * 2 + j] *= corr;
        }
        __syncwarp();

        // ---- O += P @ V ----
#pragma unroll
        for (int ks = 0; ks < 4; ks++) {
            uint32_t af[4], bf[8][2];
            LDSMX4(af[0], af[1], af[2], af[3], aP + ks * 32);
#pragma unroll
            for (int np = 0; np < 4; np++)
                LDSMX4(bf[2 * np][0], bf[2 * np][1],
                       bf[2 * np + 1][0], bf[2 * np + 1][1],
                       bV0 + bufo + np * (16 * SF * 2) + ks * 32);
#pragma unroll
            for (int nt = 0; nt < 8; nt++)
                mma_f16(acc[nt], af, bf[nt], acc[nt]);
        }

        __syncthreads();      // all reads of buf(it) done
        if (it + 2 < NKT) {   // load {K,V}(it+2) into just-freed buffer
            cp16(sK + bufo, gK); cp16(sK + bufo + 16, gK + 8);
            cp16(sV + bufo, gV); cp16(sV + bufo + 16, gV + 8);
        }
        cpcommit();
        gK += 64 * D_MODEL;
        gV += 64;
    }

    // ---- epilogue ----
#pragma unroll
    for (int rh = 0; rh < 2; rh++) {
        const float inv = 1.0f / li[rh];
        const int row = q0 + warp * 16 + tm + rh * 8;
        __half* orow = Og + (size_t)(b * SEQ + row) * D_MODEL + h * HEAD_DIM;
#pragma unroll
        for (int nt = 0; nt < 8; nt++) {
            const int col = nt * 8 + 2 * tk;
            *(__half2*)(orow + col) =
                __floats2half2_rn(acc[nt][rh * 2] * inv, acc[nt][rh * 2 + 1] * inv);
        }
    }
}

// ---------------------------------------------------------------------------
extern "C" void kernel_launch(void* const* d_in, const int* in_sizes, int n_in,
                              void* d_out, int out_size)
{
    const float* x  = (const float*)d_in[0];
    const float* Wq = (const float*)d_in[1];
    const float* bq = (const float*)d_in[2];
    const float* Wk = (const float*)d_in[3];
    const float* bk = (const float*)d_in[4];
    const float* Wv = (const float*)d_in[5];
    const float* bv = (const float*)d_in[6];
    const float* Wo = (const float*)d_in[7];
    const float* bo = (const float*)d_in[8];
    float* out = (float*)d_out;

    __half *Qd, *Kd, *VTd, *Od, *Xd, *Wd;
    cudaGetSymbolAddress((void**)&Qd, g_Q);
    cudaGetSymbolAddress((void**)&Kd, g_K);
    cudaGetSymbolAddress((void**)&VTd, g_VT);
    cudaGetSymbolAddress((void**)&Od, g_O);
    cudaGetSymbolAddress((void**)&Xd, g_X);
    cudaGetSymbolAddress((void**)&Wd, g_W);

    static int init = 0;
    if (!init) {
        cudaFuncSetAttribute(gemm_f16,
                             cudaFuncAttributeMaxDynamicSharedMemorySize, 110592);
        cudaFuncSetAttribute(flash_f16,
                             cudaFuncAttributeMaxDynamicSharedMemorySize, 73728);
        init = 1;
    }

    preround<<<2048, 256>>>(x, Wq, Wk, Wv, Wo, Xd, Wd);

    __half* Wqh = Wd;
    __half* Wkh = Wd + 1048576;
    __half* Wvh = Wd + 2097152;
    __half* Woh = Wd + 3145728;

    dim3 qkv_grid(D_MODEL / 128, MTOT / 128, 3);  // (8, 32, 3)
    gemm_f16<<<qkv_grid, 256, 110592>>>(Xd, Wqh, Wkh, Wvh, bq, bk, bv,
                                        Qd, Kd, VTd, 1, 2, 3);

    dim3 attn_grid(SEQ / 128, BATCH * NUM_HEAD);  // (16, 32)
    flash_f16<<<attn_grid, 256, 73728>>>(Qd, Kd, VTd, Od);

    dim3 o_grid(D_MODEL / 128, MTOT / 128, 1);    // (8, 32, 1)
    gemm_f16<<<o_grid, 256, 110592>>>(Od, Woh, Woh, Woh, bo, bo, bo,
                                      out, out, out, 0, 0, 0);
}